// round 16
// baseline (speedup 1.0000x reference)
#include <cuda_runtime.h>
#include <cuda_fp16.h>
#include <mma.h>
#include <cstdint>

using namespace nvcuda;

constexpr int E_   = 12;
constexpr int T_   = 2048;
constexpr int H_   = 64;
constexpr int IN_  = 128;
constexpr int K3H  = 192;
constexpr int ITERS = 10;
constexpr int KTOT = E_*H_ + H_;    // 832

// ---------------------------------------------------------------------------
// Device scratch (hi/lo fp16 split representations)
// ---------------------------------------------------------------------------
__device__ __half g_eh[(size_t)E_*T_*T_];   // edge hi  [e][s][t]
__device__ __half g_el[(size_t)E_*T_*T_];   // edge lo  [e][s][t]
__device__ __half g_hh[T_*H_],  g_hl[T_*H_];    // hidden hi/lo  [s][h]
__device__ float  g_actf[2][(size_t)E_*T_*H_];  // K1 split-K partial outputs
__device__ __half g_Bh[KTOT*K3H], g_Bl[KTOT*K3H];
__device__ float  g_iw[T_*K3H];
__device__ float  g_aw2[2][T_*K3H];         // K2 split-K partial outputs
__device__ float  g_hbuf[2][T_*H_];

// ---------------------------------------------------------------------------
// Helpers
// ---------------------------------------------------------------------------
__device__ __forceinline__ void cp16(void* s, const void* g) {
    unsigned sa = (unsigned)__cvta_generic_to_shared(s);
    asm volatile("cp.async.ca.shared.global [%0], [%1], 16;\n" :: "r"(sa), "l"(g));
}
__device__ __forceinline__ void cp_commit() { asm volatile("cp.async.commit_group;\n"); }

// ---------------------------------------------------------------------------
// p14: one-time conversions: edge hi/lo + hidden hi/lo + weight planes
// ---------------------------------------------------------------------------
constexpr int NB_EDGE = (int)(((size_t)E_*T_*T_/4) / 256);   // 49152 blocks
constexpr int NB_H    = (T_*H_) / 256;                       // 512 blocks
constexpr int NB_P2   = (KTOT*K3H + 255) / 256;              // 624 blocks

__global__ void p14_conv(const float* __restrict__ e, const float* __restrict__ h,
                         const float* __restrict__ w, const float* __restrict__ uzr) {
    if (blockIdx.x < NB_EDGE) {
        size_t i = (size_t)blockIdx.x * 256 + threadIdx.x;   // one float4 each
        float4 v = reinterpret_cast<const float4*>(e)[i];
        __half hx = __float2half_rn(v.x), hy = __float2half_rn(v.y);
        __half hz = __float2half_rn(v.z), hw = __float2half_rn(v.w);
        __half2* dh = reinterpret_cast<__half2*>(g_eh);
        __half2* dl = reinterpret_cast<__half2*>(g_el);
        dh[2*i]   = __halves2half2(hx, hy);
        dh[2*i+1] = __halves2half2(hz, hw);
        dl[2*i]   = __floats2half2_rn(v.x - __half2float(hx), v.y - __half2float(hy));
        dl[2*i+1] = __floats2half2_rn(v.z - __half2float(hz), v.w - __half2float(hw));
    } else if (blockIdx.x < NB_EDGE + NB_H) {
        int i = (blockIdx.x - NB_EDGE) * 256 + threadIdx.x;
        float v = h[i];
        __half hi = __float2half_rn(v);
        g_hh[i] = hi;
        g_hl[i] = __float2half_rn(v - __half2float(hi));
    } else {
        int i = (blockIdx.x - NB_EDGE - NB_H) * 256 + threadIdx.x;
        if (i >= KTOT * K3H) return;
        int k = i / K3H, n = i % K3H;
        float v;
        if (k < E_*H_) v = w[i];
        else { int j = k - E_*H_; v = (n < 2*H_) ? uzr[j*2*H_ + n] : 0.0f; }
        __half hi = __float2half_rn(v);
        g_Bh[i] = hi;
        g_Bl[i] = __float2half_rn(v - __half2float(hi));
    }
}

// ---------------------------------------------------------------------------
// p3: iw = x @ input_wzrh + bw.  128 CTAs x 16 rows, wi staged via smem.
// ---------------------------------------------------------------------------
__global__ __launch_bounds__(192) void p3_iw(const float* __restrict__ x,
                                             const float* __restrict__ wi,
                                             const float* __restrict__ bw) {
    __shared__ float xs[16][128];
    __shared__ float ws[32][192];
    const int t0  = blockIdx.x * 16;
    const int tid = threadIdx.x;                  // 0..191 == output col n

    for (int i = tid; i < 16*128; i += 192)
        xs[i >> 7][i & 127] = x[(t0 + (i >> 7)) * IN_ + (i & 127)];

    float acc[16];
    float b = bw[tid];
    #pragma unroll
    for (int r = 0; r < 16; r++) acc[r] = b;

    for (int kc = 0; kc < 4; kc++) {
        __syncthreads();                          // xs ready / prior reads done
        for (int i = tid; i < 32*192; i += 192)
            ws[i / 192][i % 192] = wi[(kc*32 + i/192) * K3H + (i % 192)];
        __syncthreads();
        #pragma unroll
        for (int k = 0; k < 32; k++) {
            float w = ws[k][tid];
            #pragma unroll
            for (int r = 0; r < 16; r++) acc[r] += xs[r][kc*32 + k] * w;
        }
    }
    #pragma unroll
    for (int r = 0; r < 16; r++) g_iw[(t0 + r) * K3H + tid] = acc[r];
}

// ---------------------------------------------------------------------------
// K1: partial act (split-K=2): C = edge^T @ h, 3-term hi/lo, single fp32 acc.
// CTA tile 128m x 64n, 4 warps (64m x 32n), 2-stage cp.async (k=32).
// (R12/R13 body — best measured)
// ---------------------------------------------------------------------------
constexpr int K1_LDA = 136;                   // 128 + 8 pad (halves)
constexpr int K1_LDB = 72;                    // 64 + 8 pad
constexpr int K1_APL = 32 * K1_LDA;           // halves per A plane per stage
constexpr int K1_BPL = 32 * K1_LDB;
constexpr int K1_STAGE = 2*K1_APL + 2*K1_BPL; // halves per stage
constexpr int K1_SMEM = 2 * K1_STAGE * 2;     // bytes = 53248

__global__ __launch_bounds__(128, 3) void k1_act() {
    extern __shared__ __half sm[];

    const int e      = blockIdx.y;
    const int m0     = blockIdx.x * 128;
    const int k_base = blockIdx.z * 1024;     // split-K half

    const int tid  = threadIdx.x;
    const int warp = tid >> 5;
    const int wm = (warp & 1) * 64;           // 2 warps along m
    const int wn = (warp >> 1) * 32;          // 2 warps along n

    const __half* Agh = g_eh + (size_t)e * T_ * T_;
    const __half* Agl = g_el + (size_t)e * T_ * T_;

    wmma::fragment<wmma::accumulator, 16,16,16, float> accM[4][2];
    #pragma unroll
    for (int i = 0; i < 4; i++)
        #pragma unroll
        for (int j = 0; j < 2; j++) wmma::fill_fragment(accM[i][j], 0.0f);

    auto load_stage = [&](int kb) {
        __half* base = sm + (kb & 1) * K1_STAGE;
        __half* Ah = base;
        __half* Al = base + K1_APL;
        __half* Bh = base + 2*K1_APL;
        __half* Bl = base + 2*K1_APL + K1_BPL;
        const int k0 = k_base + kb * 32;
        #pragma unroll
        for (int i = 0; i < 4; i++) {             // A: 512 chunks/plane
            int c = tid + i * 128;
            int r = c >> 4, mc = (c & 15) * 8;
            const size_t go = (size_t)(k0 + r) * T_ + m0 + mc;
            cp16(Ah + r*K1_LDA + mc, Agh + go);
            cp16(Al + r*K1_LDA + mc, Agl + go);
        }
        #pragma unroll
        for (int i = 0; i < 2; i++) {             // B: 256 chunks/plane
            int c = tid + i * 128;
            int r = c >> 3, nc = (c & 7) * 8;
            const size_t go = (size_t)(k0 + r) * H_ + nc;
            cp16(Bh + r*K1_LDB + nc, g_hh + go);
            cp16(Bl + r*K1_LDB + nc, g_hl + go);
        }
        cp_commit();
    };

    load_stage(0);
    for (int kb = 0; kb < 32; kb++) {
        asm volatile("cp.async.wait_group 0;\n" ::: "memory");
        __syncthreads();
        if (kb < 31) load_stage(kb + 1);          // overlaps compute below

        const __half* base = sm + (kb & 1) * K1_STAGE;
        const __half* Ah = base;
        const __half* Al = base + K1_APL;
        const __half* Bh = base + 2*K1_APL;
        const __half* Bl = base + 2*K1_APL + K1_BPL;

        #pragma unroll
        for (int kk = 0; kk < 32; kk += 16) {
            wmma::fragment<wmma::matrix_b, 16,16,16, __half, wmma::row_major> bfh[2], bfl[2];
            #pragma unroll
            for (int j = 0; j < 2; j++) {
                wmma::load_matrix_sync(bfh[j], Bh + kk*K1_LDB + wn + 16*j, K1_LDB);
                wmma::load_matrix_sync(bfl[j], Bl + kk*K1_LDB + wn + 16*j, K1_LDB);
            }
            #pragma unroll
            for (int i = 0; i < 4; i++) {
                wmma::fragment<wmma::matrix_a, 16,16,16, __half, wmma::col_major> afh, afl;
                wmma::load_matrix_sync(afh, Ah + kk*K1_LDA + wm + 16*i, K1_LDA);
                wmma::load_matrix_sync(afl, Al + kk*K1_LDA + wm + 16*i, K1_LDA);
                #pragma unroll
                for (int j = 0; j < 2; j++) {
                    wmma::mma_sync(accM[i][j], afh, bfh[j], accM[i][j]);   // main
                    wmma::mma_sync(accM[i][j], afh, bfl[j], accM[i][j]);   // cross
                    wmma::mma_sync(accM[i][j], afl, bfh[j], accM[i][j]);   // cross
                }
            }
        }
        __syncthreads();
    }

    // Direct epilogue to global (fp32 partials)
    float* dst = g_actf[blockIdx.z] + ((size_t)e * T_ + m0) * H_;
    #pragma unroll
    for (int i = 0; i < 4; i++)
        #pragma unroll
        for (int j = 0; j < 2; j++)
            wmma::store_matrix_sync(dst + (size_t)(wm + 16*i)*H_ + wn + 16*j,
                                    accM[i][j], H_, wmma::mem_row_major);
}

// ---------------------------------------------------------------------------
// K2: awzrh partials = [act | h] @ [W ; uz_ur|0], split-K=2 over the 13
// k-blocks (0-6 / 7-12).  CTA tile 32m x 64n, grid (64, 3, 2) = 384 CTAs.
// A built IN-LOADER from fp32 partials (+ ba) -> hi/lo fp16 smem (kconv fused).
// Single fp32 acc; direct store to g_aw2[z].
// ---------------------------------------------------------------------------
constexpr int K2_AL = 72;                     // A pitch (halves)
constexpr int K2_BL = 72;                     // B pitch
constexpr int K2_APL = 32 * K2_AL;            // 2304 halves per A plane/stage
constexpr int K2_BPL = 64 * K2_BL;            // 4608 halves per B plane/stage
constexpr int K2_STAGE = 2*K2_APL + 2*K2_BPL; // 13824 halves
constexpr int SMEM_K2 = 2 * K2_STAGE * 2;     // 55296 B

__global__ __launch_bounds__(128) void k2_awzrh(const float* __restrict__ ba) {
    extern __shared__ __half smem[];

    const int m0 = blockIdx.x * 32;
    const int n0 = blockIdx.y * 64;
    const int kb_lo = blockIdx.z ? 7 : 0;
    const int kb_hi = blockIdx.z ? 13 : 7;

    const int tid  = threadIdx.x;
    const int warp = tid >> 5;
    const int wm = (warp & 1) * 16, wn = (warp >> 1) * 32;

    wmma::fragment<wmma::accumulator, 16,16,16, float> acc[2];
    #pragma unroll
    for (int j = 0; j < 2; j++) wmma::fill_fragment(acc[j], 0.0f);

    // B loader (cp.async, one commit group per stage)
    auto loadB = [&](int st, int kb) {
        __half* base = smem + st * K2_STAGE;
        __half* Bh = base + 2*K2_APL;
        __half* Bl = base + 2*K2_APL + K2_BPL;
        const __half* bbh = g_Bh + (size_t)kb*64*K3H + n0;
        const __half* bbl = g_Bl + (size_t)kb*64*K3H + n0;
        #pragma unroll
        for (int i = 0; i < 4; i++) {             // 512 chunks/plane
            int c = tid + i * 128;
            int r = c >> 3, nc = (c & 7) * 8;
            cp16(Bh + r*K2_BL + nc, bbh + r*K3H + nc);
            cp16(Bl + r*K2_BL + nc, bbl + r*K3H + nc);
        }
        cp_commit();
    };

    // A converter: fp32 partial sum (+ba) -> hi/lo fp16 smem (fused kconv).
    // 32 rows x 64 cols; thread -> row = tid>>2, 16 cols at (tid&3)*16.
    const int ar = tid >> 2;
    const int ac = (tid & 3) * 16;
    auto convA = [&](int st, int kb) {
        __half* Ah = smem + st * K2_STAGE;
        __half* Al = Ah + K2_APL;
        if (kb < E_) {
            const size_t off = ((size_t)kb*T_ + m0 + ar) * H_ + ac;
            const float* p0 = g_actf[0] + off;
            const float* p1 = g_actf[1] + off;
            __half hs[16], ls[16];
            #pragma unroll
            for (int q = 0; q < 4; q++) {
                float4 a = *reinterpret_cast<const float4*>(p0 + q*4);
                float4 b = *reinterpret_cast<const float4*>(p1 + q*4);
                float v0 = a.x + b.x + ba[kb*H_ + ac + q*4 + 0];
                float v1 = a.y + b.y + ba[kb*H_ + ac + q*4 + 1];
                float v2 = a.z + b.z + ba[kb*H_ + ac + q*4 + 2];
                float v3 = a.w + b.w + ba[kb*H_ + ac + q*4 + 3];
                __half2 h01 = __floats2half2_rn(v0, v1);
                __half2 h23 = __floats2half2_rn(v2, v3);
                __half2 l01 = __floats2half2_rn(v0 - __low2float(h01), v1 - __high2float(h01));
                __half2 l23 = __floats2half2_rn(v2 - __low2float(h23), v3 - __high2float(h23));
                *reinterpret_cast<__half2*>(hs + q*4)     = h01;
                *reinterpret_cast<__half2*>(hs + q*4 + 2) = h23;
                *reinterpret_cast<__half2*>(ls + q*4)     = l01;
                *reinterpret_cast<__half2*>(ls + q*4 + 2) = l23;
            }
            *reinterpret_cast<uint4*>(Ah + ar*K2_AL + ac)     = *reinterpret_cast<uint4*>(hs);
            *reinterpret_cast<uint4*>(Ah + ar*K2_AL + ac + 8) = *reinterpret_cast<uint4*>(hs + 8);
            *reinterpret_cast<uint4*>(Al + ar*K2_AL + ac)     = *reinterpret_cast<uint4*>(ls);
            *reinterpret_cast<uint4*>(Al + ar*K2_AL + ac + 8) = *reinterpret_cast<uint4*>(ls + 8);
        } else {
            const size_t off = (size_t)(m0 + ar) * H_ + ac;
            *reinterpret_cast<uint4*>(Ah + ar*K2_AL + ac) =
                *reinterpret_cast<const uint4*>(g_hh + off);
            *reinterpret_cast<uint4*>(Ah + ar*K2_AL + ac + 8) =
                *reinterpret_cast<const uint4*>(g_hh + off + 8);
            *reinterpret_cast<uint4*>(Al + ar*K2_AL + ac) =
                *reinterpret_cast<const uint4*>(g_hl + off);
            *reinterpret_cast<uint4*>(Al + ar*K2_AL + ac + 8) =
                *reinterpret_cast<const uint4*>(g_hl + off + 8);
        }
    };

    loadB(0, kb_lo);
    convA(0, kb_lo);
    int st = 0;
    for (int kb = kb_lo; kb < kb_hi; kb++) {
        if (kb + 1 < kb_hi) {
            loadB(st ^ 1, kb + 1);               // async
            convA(st ^ 1, kb + 1);               // sync LDG+STS (stage free since prev iter)
            asm volatile("cp.async.wait_group 1;\n");
        } else {
            asm volatile("cp.async.wait_group 0;\n");
        }
        __syncthreads();                          // B(kb) visible; A(kb) visible

        const __half* base = smem + st * K2_STAGE;
        const __half* Ah = base;
        const __half* Al = base + K2_APL;
        const __half* Bh = base + 2*K2_APL;
        const __half* Bl = base + 2*K2_APL + K2_BPL;

        #pragma unroll
        for (int kk = 0; kk < 64; kk += 16) {
            wmma::fragment<wmma::matrix_a, 16,16,16, __half, wmma::row_major> afh, afl;
            wmma::load_matrix_sync(afh, Ah + wm*K2_AL + kk, K2_AL);
            wmma::load_matrix_sync(afl, Al + wm*K2_AL + kk, K2_AL);
            #pragma unroll
            for (int j = 0; j < 2; j++) {
                wmma::fragment<wmma::matrix_b, 16,16,16, __half, wmma::row_major> bfh, bfl;
                wmma::load_matrix_sync(bfh, Bh + kk*K2_BL + wn + 16*j, K2_BL);
                wmma::load_matrix_sync(bfl, Bl + kk*K2_BL + wn + 16*j, K2_BL);
                wmma::mma_sync(acc[j], afh, bfh, acc[j]);
                wmma::mma_sync(acc[j], afh, bfl, acc[j]);
                wmma::mma_sync(acc[j], afl, bfh, acc[j]);
            }
        }
        __syncthreads();                          // reads done before stage reuse
        st ^= 1;
    }

    float* dst = g_aw2[blockIdx.z] + (size_t)(m0 + wm)*K3H + n0 + wn;
    #pragma unroll
    for (int j = 0; j < 2; j++)
        wmma::store_matrix_sync(dst + 16*j, acc[j], K3H, wmma::mem_row_major);
}

// ---------------------------------------------------------------------------
// K3: gates + h_tilde + blend (fp32); awzrh = g_aw2[0]+g_aw2[1]+g_iw.
// ---------------------------------------------------------------------------
__global__ __launch_bounds__(256) void k3_update(int it, const float* __restrict__ hidden0,
                                                 float* __restrict__ dout,
                                                 const float* __restrict__ uh) {
    __shared__ float uh_s[64][65];
    __shared__ float rh_s[16][65];

    const int m0  = blockIdx.x * 16;
    const int tid = threadIdx.x;
    const float* h_in  = (it == 0) ? hidden0 : g_hbuf[(it - 1) & 1];
    float*       h_out = (it == ITERS - 1) ? dout : g_hbuf[it & 1];

    for (int i = tid; i < 64*64; i += 256) uh_s[i >> 6][i & 63] = uh[i];
    for (int i = tid; i < 16*64; i += 256) {
        int t = i >> 6, j = i & 63;
        int gt = m0 + t;
        int o = gt*K3H + H_ + j;
        float awr = g_aw2[0][o] + g_aw2[1][o] + g_iw[o];
        float r = 1.0f / (1.0f + expf(-awr));
        rh_s[t][j] = r * h_in[gt*H_ + j];
    }
    __syncthreads();

    const int t  = tid >> 4;
    const int nb = (tid & 15) << 2;
    const int gt = m0 + t;

    float acc[4];
    #pragma unroll
    for (int q = 0; q < 4; q++) {
        int o = gt*K3H + 2*H_ + nb + q;
        acc[q] = g_aw2[0][o] + g_aw2[1][o] + g_iw[o];
    }
    #pragma unroll 4
    for (int j = 0; j < 64; j++) {
        float rv = rh_s[t][j];
        #pragma unroll
        for (int q = 0; q < 4; q++) acc[q] += rv * uh_s[j][nb + q];
    }
    #pragma unroll
    for (int q = 0; q < 4; q++) {
        int n = nb + q;
        int o = gt*K3H + n;
        float awz = g_aw2[0][o] + g_aw2[1][o] + g_iw[o];
        float z  = 1.0f / (1.0f + expf(-awz));
        float hv = h_in[gt*H_ + n];
        float o2 = (1.0f - z) * hv + z * tanhf(acc[q]);
        h_out[gt*H_ + n] = o2;
        __half hi = __float2half_rn(o2);
        g_hh[gt*H_ + n] = hi;
        g_hl[gt*H_ + n] = __float2half_rn(o2 - __half2float(hi));
    }
}

// ---------------------------------------------------------------------------
// Launch: [1] p14  [2] p3  [3] k1(it0)  [4] k2 <- profiled slot.
// 3 launches per iteration (k1, k2, k3).
// ---------------------------------------------------------------------------
extern "C" void kernel_launch(void* const* d_in, const int* in_sizes, int n_in,
                              void* d_out, int out_size) {
    (void)in_sizes; (void)n_in; (void)out_size;
    const float* x      = (const float*)d_in[0];
    const float* hidden = (const float*)d_in[1];
    const float* edge   = (const float*)d_in[2];
    const float* ba     = (const float*)d_in[3];
    const float* w      = (const float*)d_in[4];
    const float* uzr    = (const float*)d_in[5];
    const float* uh     = (const float*)d_in[6];
    const float* wi     = (const float*)d_in[7];
    const float* bw     = (const float*)d_in[8];
    float* out = (float*)d_out;

    cudaFuncSetAttribute(k1_act,   cudaFuncAttributeMaxDynamicSharedMemorySize, K1_SMEM);
    cudaFuncSetAttribute(k2_awzrh, cudaFuncAttributeMaxDynamicSharedMemorySize, SMEM_K2);

    // [1] one-time conversions  [2] input projection  [3] k1(it0)  [4] k2 <- profiled
    p14_conv <<< NB_EDGE + NB_H + NB_P2, 256 >>>(edge, hidden, w, uzr);
    p3_iw    <<< T_/16, 192 >>>(x, wi, bw);
    k1_act   <<< dim3(T_/128, E_, 2), 128, K1_SMEM >>>();
    k2_awzrh <<< dim3(T_/32, 3, 2), 128, SMEM_K2 >>>(ba);
    k3_update<<< T_/16, 256 >>>(0, hidden, out, uh);

    for (int it = 1; it < ITERS; ++it) {
        k1_act   <<< dim3(T_/128, E_, 2), 128, K1_SMEM >>>();
        k2_awzrh <<< dim3(T_/32, 3, 2), 128, SMEM_K2 >>>(ba);
        k3_update<<< T_/16, 256 >>>(it, hidden, out, uh);
    }
}

// round 17
// speedup vs baseline: 1.0694x; 1.0694x over previous
#include <cuda_runtime.h>
#include <cuda_fp16.h>
#include <mma.h>
#include <cstdint>

using namespace nvcuda;

constexpr int E_   = 12;
constexpr int T_   = 2048;
constexpr int H_   = 64;
constexpr int IN_  = 128;
constexpr int K3H  = 192;
constexpr int ITERS = 10;
constexpr int KTOT = E_*H_ + H_;    // 832

// ---------------------------------------------------------------------------
// Device scratch (hi/lo fp16 split representations)
// ---------------------------------------------------------------------------
__device__ __half g_eh[(size_t)E_*T_*T_];   // edge hi  [e][s][t]
__device__ __half g_el[(size_t)E_*T_*T_];   // edge lo  [e][s][t]
__device__ __half g_hh[T_*H_],  g_hl[T_*H_];    // hidden hi/lo  [s][h]
__device__ float  g_actf[2][(size_t)E_*T_*H_];  // K1 split-K partial outputs
__device__ __half g_ah[(size_t)E_*T_*H_];   // act hi [e][t][h]
__device__ __half g_al[(size_t)E_*T_*H_];   // act lo
__device__ __half g_Bh[KTOT*K3H], g_Bl[KTOT*K3H];
__device__ float  g_iw[T_*K3H];
__device__ float  g_aw2[2][T_*K3H];         // K2 split-K partial outputs
__device__ float  g_hbuf[2][T_*H_];

// ---------------------------------------------------------------------------
// Helpers
// ---------------------------------------------------------------------------
__device__ __forceinline__ void cp16(void* s, const void* g) {
    unsigned sa = (unsigned)__cvta_generic_to_shared(s);
    asm volatile("cp.async.ca.shared.global [%0], [%1], 16;\n" :: "r"(sa), "l"(g));
}
__device__ __forceinline__ void cp_commit() { asm volatile("cp.async.commit_group;\n"); }

// ---------------------------------------------------------------------------
// p14: one-time conversions: edge hi/lo + hidden hi/lo + weight planes (p2)
// ---------------------------------------------------------------------------
constexpr int NB_EDGE = (int)(((size_t)E_*T_*T_/4) / 256);   // 49152 blocks
constexpr int NB_H    = (T_*H_) / 256;                       // 512 blocks
constexpr int NB_P2   = (KTOT*K3H + 255) / 256;              // 624 blocks

__global__ void p14_conv(const float* __restrict__ e, const float* __restrict__ h,
                         const float* __restrict__ w, const float* __restrict__ uzr) {
    if (blockIdx.x < NB_EDGE) {
        size_t i = (size_t)blockIdx.x * 256 + threadIdx.x;   // one float4 each
        float4 v = reinterpret_cast<const float4*>(e)[i];
        __half hx = __float2half_rn(v.x), hy = __float2half_rn(v.y);
        __half hz = __float2half_rn(v.z), hw = __float2half_rn(v.w);
        __half2* dh = reinterpret_cast<__half2*>(g_eh);
        __half2* dl = reinterpret_cast<__half2*>(g_el);
        dh[2*i]   = __halves2half2(hx, hy);
        dh[2*i+1] = __halves2half2(hz, hw);
        dl[2*i]   = __floats2half2_rn(v.x - __half2float(hx), v.y - __half2float(hy));
        dl[2*i+1] = __floats2half2_rn(v.z - __half2float(hz), v.w - __half2float(hw));
    } else if (blockIdx.x < NB_EDGE + NB_H) {
        int i = (blockIdx.x - NB_EDGE) * 256 + threadIdx.x;
        float v = h[i];
        __half hi = __float2half_rn(v);
        g_hh[i] = hi;
        g_hl[i] = __float2half_rn(v - __half2float(hi));
    } else {
        int i = (blockIdx.x - NB_EDGE - NB_H) * 256 + threadIdx.x;
        if (i >= KTOT * K3H) return;
        int k = i / K3H, n = i % K3H;
        float v;
        if (k < E_*H_) v = w[i];
        else { int j = k - E_*H_; v = (n < 2*H_) ? uzr[j*2*H_ + n] : 0.0f; }
        __half hi = __float2half_rn(v);
        g_Bh[i] = hi;
        g_Bl[i] = __float2half_rn(v - __half2float(hi));
    }
}

// ---------------------------------------------------------------------------
// p3: iw = x @ input_wzrh + bw.  128 CTAs x 16 rows, wi staged via smem.
// ---------------------------------------------------------------------------
__global__ __launch_bounds__(192) void p3_iw(const float* __restrict__ x,
                                             const float* __restrict__ wi,
                                             const float* __restrict__ bw) {
    __shared__ float xs[16][128];
    __shared__ float ws[32][192];
    const int t0  = blockIdx.x * 16;
    const int tid = threadIdx.x;                  // 0..191 == output col n

    for (int i = tid; i < 16*128; i += 192)
        xs[i >> 7][i & 127] = x[(t0 + (i >> 7)) * IN_ + (i & 127)];

    float acc[16];
    float b = bw[tid];
    #pragma unroll
    for (int r = 0; r < 16; r++) acc[r] = b;

    for (int kc = 0; kc < 4; kc++) {
        __syncthreads();                          // xs ready / prior reads done
        for (int i = tid; i < 32*192; i += 192)
            ws[i / 192][i % 192] = wi[(kc*32 + i/192) * K3H + (i % 192)];
        __syncthreads();
        #pragma unroll
        for (int k = 0; k < 32; k++) {
            float w = ws[k][tid];
            #pragma unroll
            for (int r = 0; r < 16; r++) acc[r] += xs[r][kc*32 + k] * w;
        }
    }
    #pragma unroll
    for (int r = 0; r < 16; r++) g_iw[(t0 + r) * K3H + tid] = acc[r];
}

// ---------------------------------------------------------------------------
// K1: partial act (split-K=2): C = edge^T @ h, 3-term hi/lo, single fp32 acc.
// CTA tile 128m x 64n, 4 warps (64m x 32n), 2-stage cp.async (k=32).
// (R12/R13 body — best measured)
// ---------------------------------------------------------------------------
constexpr int K1_LDA = 136;                   // 128 + 8 pad (halves)
constexpr int K1_LDB = 72;                    // 64 + 8 pad
constexpr int K1_APL = 32 * K1_LDA;           // halves per A plane per stage
constexpr int K1_BPL = 32 * K1_LDB;
constexpr int K1_STAGE = 2*K1_APL + 2*K1_BPL; // halves per stage
constexpr int K1_SMEM = 2 * K1_STAGE * 2;     // bytes = 53248

__global__ __launch_bounds__(128, 3) void k1_act() {
    extern __shared__ __half sm[];

    const int e      = blockIdx.y;
    const int m0     = blockIdx.x * 128;
    const int k_base = blockIdx.z * 1024;     // split-K half

    const int tid  = threadIdx.x;
    const int warp = tid >> 5;
    const int wm = (warp & 1) * 64;           // 2 warps along m
    const int wn = (warp >> 1) * 32;          // 2 warps along n

    const __half* Agh = g_eh + (size_t)e * T_ * T_;
    const __half* Agl = g_el + (size_t)e * T_ * T_;

    wmma::fragment<wmma::accumulator, 16,16,16, float> accM[4][2];
    #pragma unroll
    for (int i = 0; i < 4; i++)
        #pragma unroll
        for (int j = 0; j < 2; j++) wmma::fill_fragment(accM[i][j], 0.0f);

    auto load_stage = [&](int kb) {
        __half* base = sm + (kb & 1) * K1_STAGE;
        __half* Ah = base;
        __half* Al = base + K1_APL;
        __half* Bh = base + 2*K1_APL;
        __half* Bl = base + 2*K1_APL + K1_BPL;
        const int k0 = k_base + kb * 32;
        #pragma unroll
        for (int i = 0; i < 4; i++) {             // A: 512 chunks/plane
            int c = tid + i * 128;
            int r = c >> 4, mc = (c & 15) * 8;
            const size_t go = (size_t)(k0 + r) * T_ + m0 + mc;
            cp16(Ah + r*K1_LDA + mc, Agh + go);
            cp16(Al + r*K1_LDA + mc, Agl + go);
        }
        #pragma unroll
        for (int i = 0; i < 2; i++) {             // B: 256 chunks/plane
            int c = tid + i * 128;
            int r = c >> 3, nc = (c & 7) * 8;
            const size_t go = (size_t)(k0 + r) * H_ + nc;
            cp16(Bh + r*K1_LDB + nc, g_hh + go);
            cp16(Bl + r*K1_LDB + nc, g_hl + go);
        }
        cp_commit();
    };

    load_stage(0);
    for (int kb = 0; kb < 32; kb++) {
        asm volatile("cp.async.wait_group 0;\n" ::: "memory");
        __syncthreads();
        if (kb < 31) load_stage(kb + 1);          // overlaps compute below

        const __half* base = sm + (kb & 1) * K1_STAGE;
        const __half* Ah = base;
        const __half* Al = base + K1_APL;
        const __half* Bh = base + 2*K1_APL;
        const __half* Bl = base + 2*K1_APL + K1_BPL;

        #pragma unroll
        for (int kk = 0; kk < 32; kk += 16) {
            wmma::fragment<wmma::matrix_b, 16,16,16, __half, wmma::row_major> bfh[2], bfl[2];
            #pragma unroll
            for (int j = 0; j < 2; j++) {
                wmma::load_matrix_sync(bfh[j], Bh + kk*K1_LDB + wn + 16*j, K1_LDB);
                wmma::load_matrix_sync(bfl[j], Bl + kk*K1_LDB + wn + 16*j, K1_LDB);
            }
            #pragma unroll
            for (int i = 0; i < 4; i++) {
                wmma::fragment<wmma::matrix_a, 16,16,16, __half, wmma::col_major> afh, afl;
                wmma::load_matrix_sync(afh, Ah + kk*K1_LDA + wm + 16*i, K1_LDA);
                wmma::load_matrix_sync(afl, Al + kk*K1_LDA + wm + 16*i, K1_LDA);
                #pragma unroll
                for (int j = 0; j < 2; j++) {
                    wmma::mma_sync(accM[i][j], afh, bfh[j], accM[i][j]);   // main
                    wmma::mma_sync(accM[i][j], afh, bfl[j], accM[i][j]);   // cross
                    wmma::mma_sync(accM[i][j], afl, bfh[j], accM[i][j]);   // cross
                }
            }
        }
        __syncthreads();
    }

    // Direct epilogue to global (fp32 partials)
    float* dst = g_actf[blockIdx.z] + ((size_t)e * T_ + m0) * H_;
    #pragma unroll
    for (int i = 0; i < 4; i++)
        #pragma unroll
        for (int j = 0; j < 2; j++)
            wmma::store_matrix_sync(dst + (size_t)(wm + 16*i)*H_ + wn + 16*j,
                                    accM[i][j], H_, wmma::mem_row_major);
}

// ---------------------------------------------------------------------------
// kconv: sum split-K partials + ba -> hi/lo fp16 planes
// ---------------------------------------------------------------------------
constexpr int NB_KCONV = (E_*T_*H_/4) / 256;          // 6144

__global__ void kconv(const float* __restrict__ ba) {
    size_t gid = (size_t)blockIdx.x * 256 + threadIdx.x;   // one float4
    float4 v0 = reinterpret_cast<const float4*>(g_actf[0])[gid];
    float4 v1 = reinterpret_cast<const float4*>(g_actf[1])[gid];
    size_t i4 = gid * 4;
    int e  = (int)(i4 / (T_ * H_));
    int c0 = (int)(i4 & 63);
    float x = v0.x + v1.x + ba[e*H_ + c0];
    float y = v0.y + v1.y + ba[e*H_ + c0 + 1];
    float z = v0.z + v1.z + ba[e*H_ + c0 + 2];
    float ww = v0.w + v1.w + ba[e*H_ + c0 + 3];
    __half2 h0 = __floats2half2_rn(x, y);
    __half2 h1 = __floats2half2_rn(z, ww);
    __half2 l0 = __floats2half2_rn(x - __low2float(h0), y - __high2float(h0));
    __half2 l1 = __floats2half2_rn(z - __low2float(h1), ww - __high2float(h1));
    reinterpret_cast<__half2*>(g_ah)[gid*2]   = h0;
    reinterpret_cast<__half2*>(g_ah)[gid*2+1] = h1;
    reinterpret_cast<__half2*>(g_al)[gid*2]   = l0;
    reinterpret_cast<__half2*>(g_al)[gid*2+1] = l1;
}

// ---------------------------------------------------------------------------
// K2: awzrh partials = [act | h] @ [W ; uz_ur|0], split-K=2 over the 13
// k-blocks (0-6 / 7-12).  CTA tile 32m x 64n, grid (64, 3, 2) = 384 CTAs.
// All 3 hi/lo terms into one fp32 accumulator; direct store to g_aw2[z].
// (R13 body — best measured)
// ---------------------------------------------------------------------------
constexpr int K2_AL = 72;                     // A pitch (halves)
constexpr int K2_BL = 72;                     // B pitch
constexpr int K2_APL = 32 * K2_AL;            // 2304 halves per A plane/stage
constexpr int K2_BPL = 64 * K2_BL;            // 4608 halves per B plane/stage
constexpr int K2_STAGE = 2*K2_APL + 2*K2_BPL; // 13824 halves
constexpr int SMEM_K2 = 2 * K2_STAGE * 2;     // 55296 B

__global__ __launch_bounds__(128) void k2_awzrh() {
    extern __shared__ __half smem[];

    const int m0 = blockIdx.x * 32;
    const int n0 = blockIdx.y * 64;
    const int kb_lo = blockIdx.z ? 7 : 0;
    const int kb_hi = blockIdx.z ? 13 : 7;

    const int tid  = threadIdx.x;
    const int warp = tid >> 5;
    const int wm = (warp & 1) * 16, wn = (warp >> 1) * 32;

    wmma::fragment<wmma::accumulator, 16,16,16, float> acc[2];
    #pragma unroll
    for (int j = 0; j < 2; j++) wmma::fill_fragment(acc[j], 0.0f);

    auto load_stage = [&](int st, int kb) {
        __half* base = smem + st * K2_STAGE;
        __half* Ah = base;
        __half* Al = base + K2_APL;
        __half* Bh = base + 2*K2_APL;
        __half* Bl = base + 2*K2_APL + K2_BPL;
        const __half* bah = (kb < E_) ? (g_ah + ((size_t)kb*T_ + m0)*H_) : (g_hh + (size_t)m0*H_);
        const __half* bal = (kb < E_) ? (g_al + ((size_t)kb*T_ + m0)*H_) : (g_hl + (size_t)m0*H_);
        const __half* bbh = g_Bh + (size_t)kb*64*K3H + n0;
        const __half* bbl = g_Bl + (size_t)kb*64*K3H + n0;
        #pragma unroll
        for (int i = 0; i < 2; i++) {             // A: 256 chunks/plane
            int c = tid + i * 128;
            int r = c >> 3, nc = (c & 7) * 8;
            cp16(Ah + r*K2_AL + nc, bah + r*H_ + nc);
            cp16(Al + r*K2_AL + nc, bal + r*H_ + nc);
        }
        #pragma unroll
        for (int i = 0; i < 4; i++) {             // B: 512 chunks/plane
            int c = tid + i * 128;
            int r = c >> 3, nc = (c & 7) * 8;
            cp16(Bh + r*K2_BL + nc, bbh + r*K3H + nc);
            cp16(Bl + r*K2_BL + nc, bbl + r*K3H + nc);
        }
        cp_commit();
    };

    load_stage(0, kb_lo);
    int st = 0;
    for (int kb = kb_lo; kb < kb_hi; kb++) {
        if (kb + 1 < kb_hi) {
            load_stage(st ^ 1, kb + 1);
            asm volatile("cp.async.wait_group 1;\n");
        } else {
            asm volatile("cp.async.wait_group 0;\n");
        }
        __syncthreads();

        const __half* base = smem + st * K2_STAGE;
        const __half* Ah = base;
        const __half* Al = base + K2_APL;
        const __half* Bh = base + 2*K2_APL;
        const __half* Bl = base + 2*K2_APL + K2_BPL;

        #pragma unroll
        for (int kk = 0; kk < 64; kk += 16) {
            wmma::fragment<wmma::matrix_a, 16,16,16, __half, wmma::row_major> afh, afl;
            wmma::load_matrix_sync(afh, Ah + wm*K2_AL + kk, K2_AL);
            wmma::load_matrix_sync(afl, Al + wm*K2_AL + kk, K2_AL);
            #pragma unroll
            for (int j = 0; j < 2; j++) {
                wmma::fragment<wmma::matrix_b, 16,16,16, __half, wmma::row_major> bfh, bfl;
                wmma::load_matrix_sync(bfh, Bh + kk*K2_BL + wn + 16*j, K2_BL);
                wmma::load_matrix_sync(bfl, Bl + kk*K2_BL + wn + 16*j, K2_BL);
                wmma::mma_sync(acc[j], afh, bfh, acc[j]);
                wmma::mma_sync(acc[j], afh, bfl, acc[j]);
                wmma::mma_sync(acc[j], afl, bfh, acc[j]);
            }
        }
        __syncthreads();
        st ^= 1;
    }

    float* dst = g_aw2[blockIdx.z] + (size_t)(m0 + wm)*K3H + n0 + wn;
    #pragma unroll
    for (int j = 0; j < 2; j++)
        wmma::store_matrix_sync(dst + 16*j, acc[j], K3H, wmma::mem_row_major);
}

// ---------------------------------------------------------------------------
// K3: gates + h_tilde + blend (fp32); awzrh = g_aw2[0]+g_aw2[1]+g_iw.
// ---------------------------------------------------------------------------
__global__ __launch_bounds__(256) void k3_update(int it, const float* __restrict__ hidden0,
                                                 float* __restrict__ dout,
                                                 const float* __restrict__ uh) {
    __shared__ float uh_s[64][65];
    __shared__ float rh_s[16][65];

    const int m0  = blockIdx.x * 16;
    const int tid = threadIdx.x;
    const float* h_in  = (it == 0) ? hidden0 : g_hbuf[(it - 1) & 1];
    float*       h_out = (it == ITERS - 1) ? dout : g_hbuf[it & 1];

    for (int i = tid; i < 64*64; i += 256) uh_s[i >> 6][i & 63] = uh[i];
    for (int i = tid; i < 16*64; i += 256) {
        int t = i >> 6, j = i & 63;
        int gt = m0 + t;
        int o = gt*K3H + H_ + j;
        float awr = g_aw2[0][o] + g_aw2[1][o] + g_iw[o];
        float r = 1.0f / (1.0f + expf(-awr));
        rh_s[t][j] = r * h_in[gt*H_ + j];
    }
    __syncthreads();

    const int t  = tid >> 4;
    const int nb = (tid & 15) << 2;
    const int gt = m0 + t;

    float acc[4];
    #pragma unroll
    for (int q = 0; q < 4; q++) {
        int o = gt*K3H + 2*H_ + nb + q;
        acc[q] = g_aw2[0][o] + g_aw2[1][o] + g_iw[o];
    }
    #pragma unroll 4
    for (int j = 0; j < 64; j++) {
        float rv = rh_s[t][j];
        #pragma unroll
        for (int q = 0; q < 4; q++) acc[q] += rv * uh_s[j][nb + q];
    }
    #pragma unroll
    for (int q = 0; q < 4; q++) {
        int n = nb + q;
        int o = gt*K3H + n;
        float awz = g_aw2[0][o] + g_aw2[1][o] + g_iw[o];
        float z  = 1.0f / (1.0f + expf(-awz));
        float hv = h_in[gt*H_ + n];
        float o2 = (1.0f - z) * hv + z * tanhf(acc[q]);
        h_out[gt*H_ + n] = o2;
        __half hi = __float2half_rn(o2);
        g_hh[gt*H_ + n] = hi;
        g_hl[gt*H_ + n] = __float2half_rn(o2 - __half2float(hi));
    }
}

// ---------------------------------------------------------------------------
// Launch: [1] p14(+p2, once)  [2] k1(it0)  [3] kconv  [4] k2 <- profiled.
// 4 launches per iteration (k1, kconv, k2, k3); p2 no longer in the loop.
// ---------------------------------------------------------------------------
extern "C" void kernel_launch(void* const* d_in, const int* in_sizes, int n_in,
                              void* d_out, int out_size) {
    (void)in_sizes; (void)n_in; (void)out_size;
    const float* x      = (const float*)d_in[0];
    const float* hidden = (const float*)d_in[1];
    const float* edge   = (const float*)d_in[2];
    const float* ba     = (const float*)d_in[3];
    const float* w      = (const float*)d_in[4];
    const float* uzr    = (const float*)d_in[5];
    const float* uh     = (const float*)d_in[6];
    const float* wi     = (const float*)d_in[7];
    const float* bw     = (const float*)d_in[8];
    float* out = (float*)d_out;

    cudaFuncSetAttribute(k1_act,   cudaFuncAttributeMaxDynamicSharedMemorySize, K1_SMEM);
    cudaFuncSetAttribute(k2_awzrh, cudaFuncAttributeMaxDynamicSharedMemorySize, SMEM_K2);

    // [1] all one-time conversions  [2] k1(it0)  [3] kconv  [4] k2 <- profiled
    p14_conv <<< NB_EDGE + NB_H + NB_P2, 256 >>>(edge, hidden, w, uzr);
    k1_act   <<< dim3(T_/128, E_, 2), 128, K1_SMEM >>>();
    kconv    <<< NB_KCONV, 256 >>>(ba);
    k2_awzrh <<< dim3(T_/32, 3, 2), 128, SMEM_K2 >>>();

    // [5] input projection (needed only by k3)  [6] k3(it0)
    p3_iw    <<< T_/16, 192 >>>(x, wi, bw);
    k3_update<<< T_/16, 256 >>>(0, hidden, out, uh);

    for (int it = 1; it < ITERS; ++it) {
        k1_act   <<< dim3(T_/128, E_, 2), 128, K1_SMEM >>>();
        kconv    <<< NB_KCONV, 256 >>>(ba);
        k2_awzrh <<< dim3(T_/32, 3, 2), 128, SMEM_K2 >>>();
        k3_update<<< T_/16, 256 >>>(it, hidden, out, uh);
    }
}